// round 15
// baseline (speedup 1.0000x reference)
#include <cuda_runtime.h>
#include <cuda_fp16.h>
#include <cstdint>
#include <cstring>

#define BB 4
#define SS 1024
#define EE 1024
#define HH 16
#define DD 64
#define NE3 3072

// GEMM smem: 3 stages x (A [128][72]h + B [128][72]h) = 110592 B
#define GEMM_SMEM_BYTES (6 * 128 * 72 * 2)

// Scratch (no allocations allowed)
__device__ __half   g_Q[BB*HH*SS*DD];
__device__ __half   g_K[BB*HH*SS*DD];
__device__ uint32_t g_Vp[BB*HH*(SS/2)*DD];   // [bh][key/2][d] packed half2 k-pairs
__device__ __half   g_O[BB*HH*SS*DD];
__device__ __half   g_X[BB*SS*EE];
__device__ __half   g_WqT[NE3*EE];           // Wqkv transposed [n][k] fp16
__device__ __half   g_WoT[EE*EE];            // Wo transposed [n][k] fp16

__device__ __forceinline__ uint32_t h2u(__half2 h) {
    uint32_t u; memcpy(&u, &h, 4); return u;
}
__device__ __forceinline__ __half2 u2h(uint32_t u) {
    __half2 h; memcpy(&h, &u, 4); return h;
}

__device__ __forceinline__ void mma_f16(float* c, const uint32_t* a, const uint32_t* b) {
    asm volatile(
        "mma.sync.aligned.m16n8k16.row.col.f32.f16.f16.f32 "
        "{%0,%1,%2,%3},{%4,%5,%6,%7},{%8,%9},{%0,%1,%2,%3};"
        : "+f"(c[0]), "+f"(c[1]), "+f"(c[2]), "+f"(c[3])
        : "r"(a[0]), "r"(a[1]), "r"(a[2]), "r"(a[3]), "r"(b[0]), "r"(b[1]));
}

__device__ __forceinline__ void ldsm_x4(uint32_t* r, uint32_t addr) {
    asm volatile("ldmatrix.sync.aligned.m8n8.x4.shared.b16 {%0,%1,%2,%3}, [%4];"
                 : "=r"(r[0]), "=r"(r[1]), "=r"(r[2]), "=r"(r[3]) : "r"(addr));
}

__device__ __forceinline__ void cp_async16(uint32_t saddr, const void* gaddr) {
    asm volatile("cp.async.cg.shared.global [%0], [%1], 16;"
                 :: "r"(saddr), "l"(gaddr));
}
#define CP_COMMIT() asm volatile("cp.async.commit_group;")
#define CP_WAIT1()  asm volatile("cp.async.wait_group 1;")
#define CP_WAIT0()  asm volatile("cp.async.wait_group 0;")

// ---------------------------------------------------------------------------
// Pre-pass kernels
// ---------------------------------------------------------------------------
__global__ __launch_bounds__(256) void x2h_kernel(
    const float* __restrict__ in, __half* __restrict__ out, int n4)
{
    int i = blockIdx.x * blockDim.x + threadIdx.x;
    if (i < n4) {
        float4 v = ((const float4*)in)[i];
        uint2 r;
        r.x = h2u(__floats2half2_rn(v.x, v.y));
        r.y = h2u(__floats2half2_rn(v.z, v.w));
        ((uint2*)out)[i] = r;
    }
}

// tiled transpose: in [K][N] f32 -> out [N][K] fp16 (coalesced both sides)
__global__ __launch_bounds__(256) void transposeh_kernel(
    const float* __restrict__ in, __half* __restrict__ out, int K, int N)
{
    __shared__ float t[32][33];
    const int n0 = blockIdx.x * 32, k0 = blockIdx.y * 32;
    for (int i = threadIdx.y; i < 32; i += 8)
        t[i][threadIdx.x] = in[(size_t)(k0 + i) * N + n0 + threadIdx.x];
    __syncthreads();
    for (int i = threadIdx.y; i < 32; i += 8)
        out[(size_t)(n0 + i) * K + k0 + threadIdx.x] =
            __float2half_rn(t[threadIdx.x][i]);
}

// ---------------------------------------------------------------------------
// GEMM: block 128x128, BK=64 fp16, 8 warps (4m x 2n), warp tile 32x64,
// m16n8k16, fp32 accum, ldmatrix fragments.
// 3-stage cp.async pipeline, ONE __syncthreads per iter:
//   iter it: wait(stage it done; <=1 younger pending) -> sync
//            -> issue loads(it+2) into buf (it+2)%3 -> compute(it%3)
// Safe: buf (it+2)%3 == (it-1)%3, whose compute ended at iter it-1; the
// barrier at iter it orders all threads past it before the overwrite.
// ---------------------------------------------------------------------------
__global__ __launch_bounds__(256, 2) void qkv_gemm_tc(
    const float* __restrict__ bias)
{
    extern __shared__ __half dyn[];
    const int tid  = threadIdx.x;
    const int lane = tid & 31;
    const int warp = tid >> 5;
    const int wm   = warp >> 1;
    const int wn   = warp & 1;
    const int gid  = lane >> 2;
    const int tig  = lane & 3;
    const int rBase = blockIdx.y * 128;
    const int cBase = blockIdx.x * 128;

    float acc[2][8][4];
#pragma unroll
    for (int i = 0; i < 2; i++)
#pragma unroll
        for (int j = 0; j < 8; j++)
#pragma unroll
            for (int k = 0; k < 4; k++) acc[i][j][k] = 0.f;

    const uint32_t sBase = (uint32_t)__cvta_generic_to_shared(dyn);
    const uint32_t stA = 128 * 72 * 2;      // per-stage A (and B) bytes
    const uint32_t bOff = 3 * stA;          // B region after 3 A stages

    auto loadTile = [&](int buf, int it) {
        const int k0 = it * 64;
#pragma unroll
        for (int i = 0; i < 4; i++) {
            const int ia  = tid + i * 256;
            const int row = ia >> 3;
            const int c8  = (ia & 7) * 8;
            cp_async16(sBase + buf * stA + (row * 72 + c8) * 2,
                       g_X + (size_t)(rBase + row) * EE + k0 + c8);
            cp_async16(sBase + bOff + buf * stA + (row * 72 + c8) * 2,
                       g_WqT + (size_t)(cBase + row) * EE + k0 + c8);
        }
    };

    const uint32_t aFragBase = sBase +
        ((wm * 32 + (lane & 15)) * 72 + (lane >> 4) * 8) * 2;
    const uint32_t bFragBase = sBase + bOff +
        ((wn * 64 + (lane & 7) + (lane >> 4) * 8) * 72 + ((lane >> 3) & 1) * 8) * 2;

    loadTile(0, 0);
    CP_COMMIT();
    loadTile(1, 1);
    CP_COMMIT();

    int buf = 0;
    for (int it = 0; it < 16; ++it) {
        if (it < 15) { CP_WAIT1(); } else { CP_WAIT0(); }
        __syncthreads();
        if (it + 2 < 16) {
            int nb = buf + 2; if (nb >= 3) nb -= 3;
            loadTile(nb, it + 2);
            CP_COMMIT();
        }
        const uint32_t so = buf * stA;
#pragma unroll
        for (int ks = 0; ks < 4; ks++) {
            uint32_t af[2][4];
            ldsm_x4(af[0], aFragBase + so + ks * 32);
            ldsm_x4(af[1], aFragBase + so + 16 * 72 * 2 + ks * 32);
            uint32_t bfp[16];
#pragma unroll
            for (int ntp = 0; ntp < 4; ntp++)
                ldsm_x4(&bfp[ntp * 4], bFragBase + so + ntp * 16 * 72 * 2 + ks * 32);
#pragma unroll
            for (int mt = 0; mt < 2; mt++)
#pragma unroll
                for (int nt = 0; nt < 8; nt++)
                    mma_f16(acc[mt][nt], af[mt], &bfp[(nt >> 1) * 4 + (nt & 1) * 2]);
        }
        if (++buf == 3) buf = 0;
    }

    // epilogue: bias + fp16, scatter to Q/K (half2) and Vp (k-pair packed)
#pragma unroll
    for (int mt = 0; mt < 2; mt++)
#pragma unroll
        for (int nt = 0; nt < 8; nt++)
#pragma unroll
            for (int half_ = 0; half_ < 2; half_++) {
                const int r = rBase + wm * 32 + mt * 16 + gid + half_ * 8;
                const int c = cBase + wn * 64 + nt * 8 + 2 * tig;
                float vx = acc[mt][nt][half_ * 2 + 0] + bias[c];
                float vy = acc[mt][nt][half_ * 2 + 1] + bias[c + 1];
                const int b_ = r >> 10, s_ = r & 1023;
                const int which = c >> 10;
                const int e = c & 1023;
                const int h = e >> 6, d = e & 63;
                const int bh = b_ * HH + h;
                if (which == 2) {
                    __half* vp = (__half*)g_Vp;
                    size_t base = (((size_t)bh * (SS/2) + (s_ >> 1)) * DD + d) * 2 + (s_ & 1);
                    vp[base]     = __float2half_rn(vx);
                    vp[base + 2] = __float2half_rn(vy);
                } else {
                    __half* dst = (which == 0) ? g_Q : g_K;
                    *(uint32_t*)&dst[((size_t)bh * SS + s_) * DD + d] =
                        h2u(__floats2half2_rn(vx, vy));
                }
            }
}

// ---------------------------------------------------------------------------
// Flash attention fp16 (unchanged R13): QT=64, KT=64, m16n8k16.
// ---------------------------------------------------------------------------
#define QT 64
#define KT 64
__global__ __launch_bounds__(128) void flash_attn_tc()
{
    __shared__ __half   Ks[2][KT][72];
    __shared__ uint32_t Vs[2][KT/2][68];
    __shared__ __half   Ps[4][16][72];

    const int tid  = threadIdx.x;
    const int lane = tid & 31;
    const int warp = tid >> 5;
    const int gid  = lane >> 2;
    const int tig  = lane & 3;
    const int bh   = blockIdx.y;
    const int q0   = blockIdx.x * QT;
    const int r0   = q0 + warp * 16 + gid;
    const int r1   = r0 + 8;

    uint32_t qa[4][4];
    {
        const __half* Qb = g_Q + ((size_t)bh * SS) * DD;
        const __half2 sc2 = __floats2half2_rn(0.125f, 0.125f);
#pragma unroll
        for (int ks = 0; ks < 4; ks++) {
            uint32_t u0 = *(const uint32_t*)&Qb[(size_t)r0 * DD + ks * 16 + 2 * tig];
            uint32_t u1 = *(const uint32_t*)&Qb[(size_t)r1 * DD + ks * 16 + 2 * tig];
            uint32_t u2 = *(const uint32_t*)&Qb[(size_t)r0 * DD + ks * 16 + 2 * tig + 8];
            uint32_t u3 = *(const uint32_t*)&Qb[(size_t)r1 * DD + ks * 16 + 2 * tig + 8];
            qa[ks][0] = h2u(__hmul2(u2h(u0), sc2));
            qa[ks][1] = h2u(__hmul2(u2h(u1), sc2));
            qa[ks][2] = h2u(__hmul2(u2h(u2), sc2));
            qa[ks][3] = h2u(__hmul2(u2h(u3), sc2));
        }
    }

    float m0 = -1e30f, m1 = -1e30f, l0 = 0.f, l1 = 0.f;
    float oa[8][4];
#pragma unroll
    for (int i = 0; i < 8; i++)
#pragma unroll
        for (int j = 0; j < 4; j++) oa[i][j] = 0.f;

    const __half* Kb = g_K + ((size_t)bh * SS) * DD;
    const uint32_t* Vb = g_Vp + (size_t)bh * (SS/2) * DD;
    const uint32_t sK = (uint32_t)__cvta_generic_to_shared(&Ks[0][0][0]);
    const uint32_t sV = (uint32_t)__cvta_generic_to_shared(&Vs[0][0][0]);
    const uint32_t stK = KT * 72 * 2;
    const uint32_t stV = (KT/2) * 68 * 4;

    auto loadTile = [&](int buf, int k0) {
#pragma unroll
        for (int i = 0; i < 4; i++) {
            const int idx = tid + i * 128;
            const int key = idx >> 3;
            const int c8  = (idx & 7) * 8;
            cp_async16(sK + buf * stK + (key * 72 + c8) * 2,
                       Kb + (size_t)(k0 + key) * DD + c8);
            const int k2  = idx >> 4;
            const int c4  = (idx & 15) * 4;
            cp_async16(sV + buf * stV + (k2 * 68 + c4) * 4,
                       Vb + (size_t)(k0 / 2 + k2) * DD + c4);
        }
    };

    const int nkt = blockIdx.x + 1;
    loadTile(0, 0);
    CP_COMMIT();

    for (int kt = 0; kt < nkt; kt++) {
        if (kt + 1 < nkt) {
            loadTile((kt + 1) & 1, (kt + 1) * KT);
            CP_COMMIT();
            CP_WAIT1();
        } else {
            CP_WAIT0();
        }
        __syncthreads();
        const uint32_t* KtU = (const uint32_t*)&Ks[kt & 1][0][0];
        const uint32_t* VtU = &Vs[kt & 1][0][0];
        const int k0 = kt * KT;

        float sc[8][4];
#pragma unroll
        for (int i = 0; i < 8; i++)
#pragma unroll
            for (int j = 0; j < 4; j++) sc[i][j] = 0.f;
#pragma unroll
        for (int ks = 0; ks < 4; ks++) {
#pragma unroll
            for (int snt = 0; snt < 8; snt++) {
                uint32_t bf[2];
                const int base = (snt * 8 + gid) * 36 + ks * 8 + tig;
                bf[0] = KtU[base];
                bf[1] = KtU[base + 4];
                mma_f16(sc[snt], qa[ks], bf);
            }
        }

        float mt0 = -1e30f, mt1 = -1e30f;
#pragma unroll
        for (int snt = 0; snt < 8; snt++) {
            const int c0 = k0 + snt * 8 + 2 * tig;
            if (c0 > r0)     sc[snt][0] = -1e30f;
            if (c0 + 1 > r0) sc[snt][1] = -1e30f;
            if (c0 > r1)     sc[snt][2] = -1e30f;
            if (c0 + 1 > r1) sc[snt][3] = -1e30f;
            mt0 = fmaxf(mt0, fmaxf(sc[snt][0], sc[snt][1]));
            mt1 = fmaxf(mt1, fmaxf(sc[snt][2], sc[snt][3]));
        }
        mt0 = fmaxf(mt0, __shfl_xor_sync(0xffffffffu, mt0, 1));
        mt0 = fmaxf(mt0, __shfl_xor_sync(0xffffffffu, mt0, 2));
        mt1 = fmaxf(mt1, __shfl_xor_sync(0xffffffffu, mt1, 1));
        mt1 = fmaxf(mt1, __shfl_xor_sync(0xffffffffu, mt1, 2));

        const float nm0 = fmaxf(m0, mt0);
        const float nm1 = fmaxf(m1, mt1);
        const float al0 = __expf(m0 - nm0);
        const float al1 = __expf(m1 - nm1);
        m0 = nm0; m1 = nm1;

        float s0 = 0.f, s1 = 0.f;
#pragma unroll
        for (int snt = 0; snt < 8; snt++) {
            float p0 = __expf(sc[snt][0] - nm0);
            float p1 = __expf(sc[snt][1] - nm0);
            float p2 = __expf(sc[snt][2] - nm1);
            float p3 = __expf(sc[snt][3] - nm1);
            s0 += p0 + p1; s1 += p2 + p3;
            const int col = snt * 8 + 2 * tig;
            *(uint32_t*)&Ps[warp][gid][col]     = h2u(__floats2half2_rn(p0, p1));
            *(uint32_t*)&Ps[warp][gid + 8][col] = h2u(__floats2half2_rn(p2, p3));
        }
        s0 += __shfl_xor_sync(0xffffffffu, s0, 1);
        s0 += __shfl_xor_sync(0xffffffffu, s0, 2);
        s1 += __shfl_xor_sync(0xffffffffu, s1, 1);
        s1 += __shfl_xor_sync(0xffffffffu, s1, 2);
        l0 = l0 * al0 + s0;
        l1 = l1 * al1 + s1;

#pragma unroll
        for (int dnt = 0; dnt < 8; dnt++) {
            oa[dnt][0] *= al0; oa[dnt][1] *= al0;
            oa[dnt][2] *= al1; oa[dnt][3] *= al1;
        }
        __syncwarp();

        const uint32_t* PsU = (const uint32_t*)&Ps[warp][0][0];
#pragma unroll
        for (int ks = 0; ks < 4; ks++) {
            uint32_t af[4];
            af[0] = PsU[gid * 36 + ks * 8 + tig];
            af[1] = PsU[(gid + 8) * 36 + ks * 8 + tig];
            af[2] = PsU[gid * 36 + ks * 8 + tig + 4];
            af[3] = PsU[(gid + 8) * 36 + ks * 8 + tig + 4];
#pragma unroll
            for (int dnt = 0; dnt < 8; dnt++) {
                uint32_t bf[2];
                bf[0] = VtU[(ks * 8 + tig) * 68 + dnt * 8 + gid];
                bf[1] = VtU[(ks * 8 + tig + 4) * 68 + dnt * 8 + gid];
                mma_f16(oa[dnt], af, bf);
            }
        }
        __syncthreads();
    }

    const float inv0 = 1.f / l0;
    const float inv1 = 1.f / l1;
    __half* Ob = g_O + ((size_t)bh * SS) * DD;
#pragma unroll
    for (int dnt = 0; dnt < 8; dnt++) {
        const int col = dnt * 8 + 2 * tig;
        *(uint32_t*)&Ob[(size_t)r0 * DD + col] =
            h2u(__floats2half2_rn(oa[dnt][0] * inv0, oa[dnt][1] * inv0));
        *(uint32_t*)&Ob[(size_t)r1 * DD + col] =
            h2u(__floats2half2_rn(oa[dnt][2] * inv1, oa[dnt][3] * inv1));
    }
}

// ---------------------------------------------------------------------------
// Output projection fp16 (ldmatrix, 3-stage pipeline). A from g_O gather.
// ---------------------------------------------------------------------------
__global__ __launch_bounds__(256, 2) void out_gemm_tc(
    const float* __restrict__ bias, float* __restrict__ out)
{
    extern __shared__ __half dyn[];
    const int tid  = threadIdx.x;
    const int lane = tid & 31;
    const int warp = tid >> 5;
    const int wm   = warp >> 1;
    const int wn   = warp & 1;
    const int gid  = lane >> 2;
    const int tig  = lane & 3;
    const int rBase = blockIdx.y * 128;
    const int cBase = blockIdx.x * 128;

    float acc[2][8][4];
#pragma unroll
    for (int i = 0; i < 2; i++)
#pragma unroll
        for (int j = 0; j < 8; j++)
#pragma unroll
            for (int k = 0; k < 4; k++) acc[i][j][k] = 0.f;

    const uint32_t sBase = (uint32_t)__cvta_generic_to_shared(dyn);
    const uint32_t stA = 128 * 72 * 2;
    const uint32_t bOff = 3 * stA;

    auto loadTile = [&](int buf, int it) {
        const int k0 = it * 64;
#pragma unroll
        for (int i = 0; i < 4; i++) {
            const int ia  = tid + i * 256;
            const int row = ia >> 3;
            const int c8  = (ia & 7) * 8;
            const int r   = rBase + row;
            const int b_  = r >> 10, s_ = r & 1023;
            const int k   = k0 + c8;
            const int h   = k >> 6, d = k & 63;
            cp_async16(sBase + buf * stA + (row * 72 + c8) * 2,
                       g_O + (((size_t)(b_ * HH + h)) * SS + s_) * DD + d);
            cp_async16(sBase + bOff + buf * stA + (row * 72 + c8) * 2,
                       g_WoT + (size_t)(cBase + row) * EE + k0 + c8);
        }
    };

    const uint32_t aFragBase = sBase +
        ((wm * 32 + (lane & 15)) * 72 + (lane >> 4) * 8) * 2;
    const uint32_t bFragBase = sBase + bOff +
        ((wn * 64 + (lane & 7) + (lane >> 4) * 8) * 72 + ((lane >> 3) & 1) * 8) * 2;

    loadTile(0, 0);
    CP_COMMIT();
    loadTile(1, 1);
    CP_COMMIT();

    int buf = 0;
    for (int it = 0; it < 16; ++it) {
        if (it < 15) { CP_WAIT1(); } else { CP_WAIT0(); }
        __syncthreads();
        if (it + 2 < 16) {
            int nb = buf + 2; if (nb >= 3) nb -= 3;
            loadTile(nb, it + 2);
            CP_COMMIT();
        }
        const uint32_t so = buf * stA;
#pragma unroll
        for (int ks = 0; ks < 4; ks++) {
            uint32_t af[2][4];
            ldsm_x4(af[0], aFragBase + so + ks * 32);
            ldsm_x4(af[1], aFragBase + so + 16 * 72 * 2 + ks * 32);
            uint32_t bfp[16];
#pragma unroll
            for (int ntp = 0; ntp < 4; ntp++)
                ldsm_x4(&bfp[ntp * 4], bFragBase + so + ntp * 16 * 72 * 2 + ks * 32);
#pragma unroll
            for (int mt = 0; mt < 2; mt++)
#pragma unroll
                for (int nt = 0; nt < 8; nt++)
                    mma_f16(acc[mt][nt], af[mt], &bfp[(nt >> 1) * 4 + (nt & 1) * 2]);
        }
        if (++buf == 3) buf = 0;
    }

#pragma unroll
    for (int mt = 0; mt < 2; mt++)
#pragma unroll
        for (int nt = 0; nt < 8; nt++)
#pragma unroll
            for (int half_ = 0; half_ < 2; half_++) {
                const int r = rBase + wm * 32 + mt * 16 + gid + half_ * 8;
                const int c = cBase + wn * 64 + nt * 8 + 2 * tig;
                float2 v;
                v.x = acc[mt][nt][half_ * 2 + 0] + bias[c];
                v.y = acc[mt][nt][half_ * 2 + 1] + bias[c + 1];
                *(float2*)&out[(size_t)r * EE + c] = v;
            }
}

// ---------------------------------------------------------------------------
extern "C" void kernel_launch(void* const* d_in, const int* in_sizes, int n_in,
                              void* d_out, int out_size)
{
    const float* x = (const float*)d_in[0];
    const float* Wqkv = (const float*)d_in[2];
    const float* bqkv = (const float*)d_in[3];
    const float* Wo = (const float*)d_in[4];
    const float* bo = (const float*)d_in[5];
    float* out = (float*)d_out;

    __half* gX;  cudaGetSymbolAddress((void**)&gX,  g_X);
    __half* gWq; cudaGetSymbolAddress((void**)&gWq, g_WqT);
    __half* gWo; cudaGetSymbolAddress((void**)&gWo, g_WoT);

    cudaFuncSetAttribute(qkv_gemm_tc,
        cudaFuncAttributeMaxDynamicSharedMemorySize, GEMM_SMEM_BYTES);
    cudaFuncSetAttribute(out_gemm_tc,
        cudaFuncAttributeMaxDynamicSharedMemorySize, GEMM_SMEM_BYTES);

    x2h_kernel<<<(BB*SS*EE/4 + 255)/256, 256>>>(x, gX, BB*SS*EE/4);
    {
        dim3 grid(NE3/32, EE/32);
        transposeh_kernel<<<grid, dim3(32,8)>>>(Wqkv, gWq, EE, NE3);
    }
    {
        dim3 grid(EE/32, EE/32);
        transposeh_kernel<<<grid, dim3(32,8)>>>(Wo, gWo, EE, EE);
    }
    {
        dim3 grid(NE3 / 128, (BB * SS) / 128);   // (24, 32)
        qkv_gemm_tc<<<grid, 256, GEMM_SMEM_BYTES>>>(bqkv);
    }
    {
        dim3 grid(SS / QT, BB * HH);             // (16, 64)
        flash_attn_tc<<<grid, 128>>>();
    }
    {
        dim3 grid(EE / 128, (BB * SS) / 128);    // (8, 32)
        out_gemm_tc<<<grid, 256, GEMM_SMEM_BYTES>>>(bo, out);
    }
}

// round 17
// speedup vs baseline: 1.0590x; 1.0590x over previous
#include <cuda_runtime.h>
#include <cuda_fp16.h>
#include <cstdint>
#include <cstring>

#define BB 4
#define SS 1024
#define EE 1024
#define HH 16
#define DD 64
#define NE3 3072

// GEMM smem: A 2 stages [128][72] half + B 2 stages [128][72] half
#define GEMM_SMEM_BYTES (4 * 128 * 72 * 2)   // 73728

// Scratch (no allocations allowed)
__device__ __half   g_Q[BB*HH*SS*DD];
__device__ __half   g_K[BB*HH*SS*DD];
__device__ uint32_t g_Vp[BB*HH*(SS/2)*DD];   // [bh][key/2][d] packed half2 k-pairs
__device__ __half   g_O[BB*HH*SS*DD];
__device__ __half   g_X[BB*SS*EE];
__device__ __half   g_WqT[NE3*EE];           // Wqkv transposed [n][k] fp16
__device__ __half   g_WoT[EE*EE];            // Wo transposed [n][k] fp16

__device__ __forceinline__ uint32_t h2u(__half2 h) {
    uint32_t u; memcpy(&u, &h, 4); return u;
}
__device__ __forceinline__ __half2 u2h(uint32_t u) {
    __half2 h; memcpy(&h, &u, 4); return h;
}
__device__ __forceinline__ float ex2(float x) {
    float y; asm("ex2.approx.ftz.f32 %0, %1;" : "=f"(y) : "f"(x)); return y;
}

__device__ __forceinline__ void mma_f16(float* c, const uint32_t* a, const uint32_t* b) {
    asm volatile(
        "mma.sync.aligned.m16n8k16.row.col.f32.f16.f16.f32 "
        "{%0,%1,%2,%3},{%4,%5,%6,%7},{%8,%9},{%0,%1,%2,%3};"
        : "+f"(c[0]), "+f"(c[1]), "+f"(c[2]), "+f"(c[3])
        : "r"(a[0]), "r"(a[1]), "r"(a[2]), "r"(a[3]), "r"(b[0]), "r"(b[1]));
}

__device__ __forceinline__ void ldsm_x4(uint32_t* r, uint32_t addr) {
    asm volatile("ldmatrix.sync.aligned.m8n8.x4.shared.b16 {%0,%1,%2,%3}, [%4];"
                 : "=r"(r[0]), "=r"(r[1]), "=r"(r[2]), "=r"(r[3]) : "r"(addr));
}

__device__ __forceinline__ void cp_async16(uint32_t saddr, const void* gaddr) {
    asm volatile("cp.async.cg.shared.global [%0], [%1], 16;"
                 :: "r"(saddr), "l"(gaddr));
}
#define CP_COMMIT() asm volatile("cp.async.commit_group;")
#define CP_WAIT1()  asm volatile("cp.async.wait_group 1;")
#define CP_WAIT0()  asm volatile("cp.async.wait_group 0;")

// ---------------------------------------------------------------------------
// Pre-pass kernels (R14-proven)
// ---------------------------------------------------------------------------
__global__ __launch_bounds__(256) void x2h_kernel(
    const float* __restrict__ in, __half* __restrict__ out, int n4)
{
    int i = blockIdx.x * blockDim.x + threadIdx.x;
    if (i < n4) {
        float4 v = ((const float4*)in)[i];
        uint2 r;
        r.x = h2u(__floats2half2_rn(v.x, v.y));
        r.y = h2u(__floats2half2_rn(v.z, v.w));
        ((uint2*)out)[i] = r;
    }
}

__global__ __launch_bounds__(256) void transposeh_kernel(
    const float* __restrict__ in, __half* __restrict__ out, int K, int N)
{
    __shared__ float t[32][33];
    const int n0 = blockIdx.x * 32, k0 = blockIdx.y * 32;
    for (int i = threadIdx.y; i < 32; i += 8)
        t[i][threadIdx.x] = in[(size_t)(k0 + i) * N + n0 + threadIdx.x];
    __syncthreads();
    for (int i = threadIdx.y; i < 32; i += 8)
        out[(size_t)(n0 + i) * K + k0 + threadIdx.x] =
            __float2half_rn(t[threadIdx.x][i]);
}

// ---------------------------------------------------------------------------
// GEMM (R14-proven): block 128x128, BK=64 fp16, 8 warps, warp tile 32x64,
// m16n8k16, ldmatrix fragments, 2-stage cp.async, 2 CTAs/SM.
// ---------------------------------------------------------------------------
__global__ __launch_bounds__(256, 2) void qkv_gemm_tc(
    const float* __restrict__ bias)
{
    extern __shared__ __half dyn[];
    const int tid  = threadIdx.x;
    const int lane = tid & 31;
    const int warp = tid >> 5;
    const int wm   = warp >> 1;
    const int wn   = warp & 1;
    const int gid  = lane >> 2;
    const int tig  = lane & 3;
    const int rBase = blockIdx.y * 128;
    const int cBase = blockIdx.x * 128;

    float acc[2][8][4];
#pragma unroll
    for (int i = 0; i < 2; i++)
#pragma unroll
        for (int j = 0; j < 8; j++)
#pragma unroll
            for (int k = 0; k < 4; k++) acc[i][j][k] = 0.f;

    const uint32_t sBase = (uint32_t)__cvta_generic_to_shared(dyn);
    const uint32_t stA = 128 * 72 * 2;
    const uint32_t bOff = 2 * stA;

    auto loadTile = [&](int buf, int it) {
        const int k0 = it * 64;
#pragma unroll
        for (int i = 0; i < 4; i++) {
            const int ia  = tid + i * 256;
            const int row = ia >> 3;
            const int c8  = (ia & 7) * 8;
            cp_async16(sBase + buf * stA + (row * 72 + c8) * 2,
                       g_X + (size_t)(rBase + row) * EE + k0 + c8);
            cp_async16(sBase + bOff + buf * stA + (row * 72 + c8) * 2,
                       g_WqT + (size_t)(cBase + row) * EE + k0 + c8);
        }
    };

    const uint32_t aFragBase = sBase +
        ((wm * 32 + (lane & 15)) * 72 + (lane >> 4) * 8) * 2;
    const uint32_t bFragBase = sBase + bOff +
        ((wn * 64 + (lane & 7) + (lane >> 4) * 8) * 72 + ((lane >> 3) & 1) * 8) * 2;

    loadTile(0, 0);
    CP_COMMIT();

    for (int it = 0; it < 16; ++it) {
        if (it + 1 < 16) {
            loadTile((it + 1) & 1, it + 1);
            CP_COMMIT();
            CP_WAIT1();
        } else {
            CP_WAIT0();
        }
        __syncthreads();
        const uint32_t so = (it & 1) * stA;
#pragma unroll
        for (int ks = 0; ks < 4; ks++) {
            uint32_t af[2][4];
            ldsm_x4(af[0], aFragBase + so + ks * 32);
            ldsm_x4(af[1], aFragBase + so + 16 * 72 * 2 + ks * 32);
            uint32_t bfp[16];
#pragma unroll
            for (int ntp = 0; ntp < 4; ntp++)
                ldsm_x4(&bfp[ntp * 4], bFragBase + so + ntp * 16 * 72 * 2 + ks * 32);
#pragma unroll
            for (int mt = 0; mt < 2; mt++)
#pragma unroll
                for (int nt = 0; nt < 8; nt++)
                    mma_f16(acc[mt][nt], af[mt], &bfp[(nt >> 1) * 4 + (nt & 1) * 2]);
        }
        __syncthreads();
    }

#pragma unroll
    for (int mt = 0; mt < 2; mt++)
#pragma unroll
        for (int nt = 0; nt < 8; nt++)
#pragma unroll
            for (int half_ = 0; half_ < 2; half_++) {
                const int r = rBase + wm * 32 + mt * 16 + gid + half_ * 8;
                const int c = cBase + wn * 64 + nt * 8 + 2 * tig;
                float vx = acc[mt][nt][half_ * 2 + 0] + bias[c];
                float vy = acc[mt][nt][half_ * 2 + 1] + bias[c + 1];
                const int b_ = r >> 10, s_ = r & 1023;
                const int which = c >> 10;
                const int e = c & 1023;
                const int h = e >> 6, d = e & 63;
                const int bh = b_ * HH + h;
                if (which == 2) {
                    __half* vp = (__half*)g_Vp;
                    size_t base = (((size_t)bh * (SS/2) + (s_ >> 1)) * DD + d) * 2 + (s_ & 1);
                    vp[base]     = __float2half_rn(vx);
                    vp[base + 2] = __float2half_rn(vy);
                } else {
                    __half* dst = (which == 0) ? g_Q : g_K;
                    *(uint32_t*)&dst[((size_t)bh * SS + s_) * DD + d] =
                        h2u(__floats2half2_rn(vx, vy));
                }
            }
}

// ---------------------------------------------------------------------------
// Flash attention fp16: QT=64, KT=64, m16n8k16.
// NEW: P stays in registers — QK C-fragments (c0..c3 per snt tile) ARE the
// PV A-fragments (af = {pa[2ks][0], pa[2ks][1], pa[2ks+1][0], pa[2ks+1][1]}).
// No Ps smem, no __syncwarp. exp via ex2 with log2e folded into Q scale.
// ---------------------------------------------------------------------------
#define QT 64
#define KT 64
__global__ __launch_bounds__(128) void flash_attn_tc()
{
    __shared__ __half   Ks[2][KT][72];
    __shared__ uint32_t Vs[2][KT/2][68];

    const int tid  = threadIdx.x;
    const int lane = tid & 31;
    const int warp = tid >> 5;
    const int gid  = lane >> 2;
    const int tig  = lane & 3;
    const int bh   = blockIdx.y;
    const int q0   = blockIdx.x * QT;
    const int r0   = q0 + warp * 16 + gid;
    const int r1   = r0 + 8;

    // Q fragments, scaled by 0.125*log2(e): scores land in log2-domain
    uint32_t qa[4][4];
    {
        const __half* Qb = g_Q + ((size_t)bh * SS) * DD;
        const float qs = 0.125f * 1.4426950408889634f;
        const __half2 sc2 = __floats2half2_rn(qs, qs);
#pragma unroll
        for (int ks = 0; ks < 4; ks++) {
            uint32_t u0 = *(const uint32_t*)&Qb[(size_t)r0 * DD + ks * 16 + 2 * tig];
            uint32_t u1 = *(const uint32_t*)&Qb[(size_t)r1 * DD + ks * 16 + 2 * tig];
            uint32_t u2 = *(const uint32_t*)&Qb[(size_t)r0 * DD + ks * 16 + 2 * tig + 8];
            uint32_t u3 = *(const uint32_t*)&Qb[(size_t)r1 * DD + ks * 16 + 2 * tig + 8];
            qa[ks][0] = h2u(__hmul2(u2h(u0), sc2));
            qa[ks][1] = h2u(__hmul2(u2h(u1), sc2));
            qa[ks][2] = h2u(__hmul2(u2h(u2), sc2));
            qa[ks][3] = h2u(__hmul2(u2h(u3), sc2));
        }
    }

    float m0 = -1e30f, m1 = -1e30f, l0 = 0.f, l1 = 0.f;
    float oa[8][4];
#pragma unroll
    for (int i = 0; i < 8; i++)
#pragma unroll
        for (int j = 0; j < 4; j++) oa[i][j] = 0.f;

    const __half* Kb = g_K + ((size_t)bh * SS) * DD;
    const uint32_t* Vb = g_Vp + (size_t)bh * (SS/2) * DD;
    const uint32_t sK = (uint32_t)__cvta_generic_to_shared(&Ks[0][0][0]);
    const uint32_t sV = (uint32_t)__cvta_generic_to_shared(&Vs[0][0][0]);
    const uint32_t stK = KT * 72 * 2;
    const uint32_t stV = (KT/2) * 68 * 4;

    auto loadTile = [&](int buf, int k0) {
#pragma unroll
        for (int i = 0; i < 4; i++) {
            const int idx = tid + i * 128;
            const int key = idx >> 3;
            const int c8  = (idx & 7) * 8;
            cp_async16(sK + buf * stK + (key * 72 + c8) * 2,
                       Kb + (size_t)(k0 + key) * DD + c8);
            const int k2  = idx >> 4;
            const int c4  = (idx & 15) * 4;
            cp_async16(sV + buf * stV + (k2 * 68 + c4) * 4,
                       Vb + (size_t)(k0 / 2 + k2) * DD + c4);
        }
    };

    const int nkt = blockIdx.x + 1;
    loadTile(0, 0);
    CP_COMMIT();

    for (int kt = 0; kt < nkt; kt++) {
        if (kt + 1 < nkt) {
            loadTile((kt + 1) & 1, (kt + 1) * KT);
            CP_COMMIT();
            CP_WAIT1();
        } else {
            CP_WAIT0();
        }
        __syncthreads();
        const uint32_t* KtU = (const uint32_t*)&Ks[kt & 1][0][0];
        const uint32_t* VtU = &Vs[kt & 1][0][0];
        const int k0 = kt * KT;

        // S' = (Q*0.125*log2e) @ K^T : 4 ks x 8 snt MMAs
        float sc[8][4];
#pragma unroll
        for (int i = 0; i < 8; i++)
#pragma unroll
            for (int j = 0; j < 4; j++) sc[i][j] = 0.f;
#pragma unroll
        for (int ks = 0; ks < 4; ks++) {
#pragma unroll
            for (int snt = 0; snt < 8; snt++) {
                uint32_t bf[2];
                const int base = (snt * 8 + gid) * 36 + ks * 8 + tig;
                bf[0] = KtU[base];
                bf[1] = KtU[base + 4];
                mma_f16(sc[snt], qa[ks], bf);
            }
        }

        float mt0 = -1e30f, mt1 = -1e30f;
#pragma unroll
        for (int snt = 0; snt < 8; snt++) {
            const int c0 = k0 + snt * 8 + 2 * tig;
            if (c0 > r0)     sc[snt][0] = -1e30f;
            if (c0 + 1 > r0) sc[snt][1] = -1e30f;
            if (c0 > r1)     sc[snt][2] = -1e30f;
            if (c0 + 1 > r1) sc[snt][3] = -1e30f;
            mt0 = fmaxf(mt0, fmaxf(sc[snt][0], sc[snt][1]));
            mt1 = fmaxf(mt1, fmaxf(sc[snt][2], sc[snt][3]));
        }
        mt0 = fmaxf(mt0, __shfl_xor_sync(0xffffffffu, mt0, 1));
        mt0 = fmaxf(mt0, __shfl_xor_sync(0xffffffffu, mt0, 2));
        mt1 = fmaxf(mt1, __shfl_xor_sync(0xffffffffu, mt1, 1));
        mt1 = fmaxf(mt1, __shfl_xor_sync(0xffffffffu, mt1, 2));

        const float nm0 = fmaxf(m0, mt0);
        const float nm1 = fmaxf(m1, mt1);
        const float al0 = ex2(m0 - nm0);    // 2^x: scores in log2 domain
        const float al1 = ex2(m1 - nm1);
        m0 = nm0; m1 = nm1;

        // probabilities -> fp16 PV A-fragments, entirely in registers
        float s0 = 0.f, s1 = 0.f;
        uint32_t pa[8][2];
#pragma unroll
        for (int snt = 0; snt < 8; snt++) {
            float p0 = ex2(sc[snt][0] - nm0);
            float p1 = ex2(sc[snt][1] - nm0);
            float p2 = ex2(sc[snt][2] - nm1);
            float p3 = ex2(sc[snt][3] - nm1);
            s0 += p0 + p1; s1 += p2 + p3;
            pa[snt][0] = h2u(__floats2half2_rn(p0, p1));   // rows gid
            pa[snt][1] = h2u(__floats2half2_rn(p2, p3));   // rows gid+8
        }
        s0 += __shfl_xor_sync(0xffffffffu, s0, 1);
        s0 += __shfl_xor_sync(0xffffffffu, s0, 2);
        s1 += __shfl_xor_sync(0xffffffffu, s1, 1);
        s1 += __shfl_xor_sync(0xffffffffu, s1, 2);
        l0 = l0 * al0 + s0;
        l1 = l1 * al1 + s1;

#pragma unroll
        for (int dnt = 0; dnt < 8; dnt++) {
            oa[dnt][0] *= al0; oa[dnt][1] *= al0;
            oa[dnt][2] *= al1; oa[dnt][3] *= al1;
        }

        // PV: 4 ks x 8 dnt MMAs, A-fragments straight from pa[]
#pragma unroll
        for (int ks = 0; ks < 4; ks++) {
            uint32_t af[4];
            af[0] = pa[2 * ks][0];
            af[1] = pa[2 * ks][1];
            af[2] = pa[2 * ks + 1][0];
            af[3] = pa[2 * ks + 1][1];
#pragma unroll
            for (int dnt = 0; dnt < 8; dnt++) {
                uint32_t bf[2];
                bf[0] = VtU[(ks * 8 + tig) * 68 + dnt * 8 + gid];
                bf[1] = VtU[(ks * 8 + tig + 4) * 68 + dnt * 8 + gid];
                mma_f16(oa[dnt], af, bf);
            }
        }
        __syncthreads();
    }

    const float inv0 = 1.f / l0;
    const float inv1 = 1.f / l1;
    __half* Ob = g_O + ((size_t)bh * SS) * DD;
#pragma unroll
    for (int dnt = 0; dnt < 8; dnt++) {
        const int col = dnt * 8 + 2 * tig;
        *(uint32_t*)&Ob[(size_t)r0 * DD + col] =
            h2u(__floats2half2_rn(oa[dnt][0] * inv0, oa[dnt][1] * inv0));
        *(uint32_t*)&Ob[(size_t)r1 * DD + col] =
            h2u(__floats2half2_rn(oa[dnt][2] * inv1, oa[dnt][3] * inv1));
    }
}

// ---------------------------------------------------------------------------
// Output projection fp16 (R14-proven ldmatrix version).
// ---------------------------------------------------------------------------
__global__ __launch_bounds__(256, 2) void out_gemm_tc(
    const float* __restrict__ bias, float* __restrict__ out)
{
    extern __shared__ __half dyn[];
    const int tid  = threadIdx.x;
    const int lane = tid & 31;
    const int warp = tid >> 5;
    const int wm   = warp >> 1;
    const int wn   = warp & 1;
    const int gid  = lane >> 2;
    const int tig  = lane & 3;
    const int rBase = blockIdx.y * 128;
    const int cBase = blockIdx.x * 128;

    float acc[2][8][4];
#pragma unroll
    for (int i = 0; i < 2; i++)
#pragma unroll
        for (int j = 0; j < 8; j++)
#pragma unroll
            for (int k = 0; k < 4; k++) acc[i][j][k] = 0.f;

    const uint32_t sBase = (uint32_t)__cvta_generic_to_shared(dyn);
    const uint32_t stA = 128 * 72 * 2;
    const uint32_t bOff = 2 * stA;

    auto loadTile = [&](int buf, int it) {
        const int k0 = it * 64;
#pragma unroll
        for (int i = 0; i < 4; i++) {
            const int ia  = tid + i * 256;
            const int row = ia >> 3;
            const int c8  = (ia & 7) * 8;
            const int r   = rBase + row;
            const int b_  = r >> 10, s_ = r & 1023;
            const int k   = k0 + c8;
            const int h   = k >> 6, d = k & 63;
            cp_async16(sBase + buf * stA + (row * 72 + c8) * 2,
                       g_O + (((size_t)(b_ * HH + h)) * SS + s_) * DD + d);
            cp_async16(sBase + bOff + buf * stA + (row * 72 + c8) * 2,
                       g_WoT + (size_t)(cBase + row) * EE + k0 + c8);
        }
    };

    const uint32_t aFragBase = sBase +
        ((wm * 32 + (lane & 15)) * 72 + (lane >> 4) * 8) * 2;
    const uint32_t bFragBase = sBase + bOff +
        ((wn * 64 + (lane & 7) + (lane >> 4) * 8) * 72 + ((lane >> 3) & 1) * 8) * 2;

    loadTile(0, 0);
    CP_COMMIT();

    for (int it = 0; it < 16; ++it) {
        if (it + 1 < 16) {
            loadTile((it + 1) & 1, it + 1);
            CP_COMMIT();
            CP_WAIT1();
        } else {
            CP_WAIT0();
        }
        __syncthreads();
        const uint32_t so = (it & 1) * stA;
#pragma unroll
        for (int ks = 0; ks < 4; ks++) {
            uint32_t af[2][4];
            ldsm_x4(af[0], aFragBase + so + ks * 32);
            ldsm_x4(af[1], aFragBase + so + 16 * 72 * 2 + ks * 32);
            uint32_t bfp[16];
#pragma unroll
            for (int ntp = 0; ntp < 4; ntp++)
                ldsm_x4(&bfp[ntp * 4], bFragBase + so + ntp * 16 * 72 * 2 + ks * 32);
#pragma unroll
            for (int mt = 0; mt < 2; mt++)
#pragma unroll
                for (int nt = 0; nt < 8; nt++)
                    mma_f16(acc[mt][nt], af[mt], &bfp[(nt >> 1) * 4 + (nt & 1) * 2]);
        }
        __syncthreads();
    }

#pragma unroll
    for (int mt = 0; mt < 2; mt++)
#pragma unroll
        for (int nt = 0; nt < 8; nt++)
#pragma unroll
            for (int half_ = 0; half_ < 2; half_++) {
                const int r = rBase + wm * 32 + mt * 16 + gid + half_ * 8;
                const int c = cBase + wn * 64 + nt * 8 + 2 * tig;
                float2 v;
                v.x = acc[mt][nt][half_ * 2 + 0] + bias[c];
                v.y = acc[mt][nt][half_ * 2 + 1] + bias[c + 1];
                *(float2*)&out[(size_t)r * EE + c] = v;
            }
}

// ---------------------------------------------------------------------------
extern "C" void kernel_launch(void* const* d_in, const int* in_sizes, int n_in,
                              void* d_out, int out_size)
{
    const float* x = (const float*)d_in[0];
    const float* Wqkv = (const float*)d_in[2];
    const float* bqkv = (const float*)d_in[3];
    const float* Wo = (const float*)d_in[4];
    const float* bo = (const float*)d_in[5];
    float* out = (float*)d_out;

    __half* gX;  cudaGetSymbolAddress((void**)&gX,  g_X);
    __half* gWq; cudaGetSymbolAddress((void**)&gWq, g_WqT);
    __half* gWo; cudaGetSymbolAddress((void**)&gWo, g_WoT);

    cudaFuncSetAttribute(qkv_gemm_tc,
        cudaFuncAttributeMaxDynamicSharedMemorySize, GEMM_SMEM_BYTES);
    cudaFuncSetAttribute(out_gemm_tc,
        cudaFuncAttributeMaxDynamicSharedMemorySize, GEMM_SMEM_BYTES);

    x2h_kernel<<<(BB*SS*EE/4 + 255)/256, 256>>>(x, gX, BB*SS*EE/4);
    {
        dim3 grid(NE3/32, EE/32);
        transposeh_kernel<<<grid, dim3(32,8)>>>(Wqkv, gWq, EE, NE3);
    }
    {
        dim3 grid(EE/32, EE/32);
        transposeh_kernel<<<grid, dim3(32,8)>>>(Wo, gWo, EE, EE);
    }
    {
        dim3 grid(NE3 / 128, (BB * SS) / 128);   // (24, 32)
        qkv_gemm_tc<<<grid, 256, GEMM_SMEM_BYTES>>>(bqkv);
    }
    {
        dim3 grid(SS / QT, BB * HH);             // (16, 64)
        flash_attn_tc<<<grid, 128>>>();
    }
    {
        dim3 grid(EE / 128, (BB * SS) / 128);    // (8, 32)
        out_gemm_tc<<<grid, 256, GEMM_SMEM_BYTES>>>(bo, out);
    }
}